// round 1
// baseline (speedup 1.0000x reference)
#include <cuda_runtime.h>

#define B_    4
#define T_    2048
#define EMB_  2048
#define HD_   128
#define HALF_ 64
#define MTOT  (B_*T_)   // 8192

// Scratch for projected Q/K/V (post-RoPE). 4 MB each.
__device__ float g_Q[MTOT*HD_];
__device__ float g_K[MTOT*HD_];
__device__ float g_V[MTOT*HD_];

// ---------------------------------------------------------------------------
// Kernel 1: fused QKV projection + RoPE.
// Grid: (MTOT/BM, 3). blockIdx.y selects Q/K/V. 256 threads.
// Each block: BM=64 rows x 128 cols, K tiled by 32.
// Thread computes 4x8 register tile (16x16 thread grid).
// ---------------------------------------------------------------------------
#define BM 64
#define KT 32

__global__ __launch_bounds__(256, 2) void qkv_kernel(
    const float* __restrict__ x, const float* __restrict__ Wq,
    const float* __restrict__ Wk, const float* __restrict__ Wv,
    const float* __restrict__ rc, const float* __restrict__ rs)
{
    __shared__ float sAT[KT][BM+4];   // x tile, transposed, padded (conflict control)
    __shared__ float sB[KT][HD_];     // W tile

    const int which = blockIdx.y;
    const float* __restrict__ W   = (which==0) ? Wq : ((which==1) ? Wk : Wv);
    float*       __restrict__ dst = (which==0) ? g_Q : ((which==1) ? g_K : g_V);

    const int m0  = blockIdx.x * BM;
    const int tid = threadIdx.x;
    const int tr  = tid >> 4;    // 0..15 -> rows tr*4..tr*4+3
    const int tc  = tid & 15;    // 0..15 -> cols tc*8..tc*8+7

    float acc[4][8];
    #pragma unroll
    for (int i = 0; i < 4; i++)
        #pragma unroll
        for (int j = 0; j < 8; j++) acc[i][j] = 0.f;

    for (int k0 = 0; k0 < EMB_; k0 += KT) {
        // load x tile (64 rows x 32 cols) transposed into sAT
        #pragma unroll
        for (int it = 0; it < 2; it++) {
            int idx = tid + it*256;            // 0..511 float4s
            int r   = idx >> 3;                // 0..63
            int c4  = idx & 7;                 // 0..7
            float4 v = *reinterpret_cast<const float4*>(
                &x[(size_t)(m0 + r)*EMB_ + k0 + c4*4]);
            sAT[c4*4+0][r] = v.x;
            sAT[c4*4+1][r] = v.y;
            sAT[c4*4+2][r] = v.z;
            sAT[c4*4+3][r] = v.w;
        }
        // load W tile (32 rows x 128 cols)
        #pragma unroll
        for (int it = 0; it < 4; it++) {
            int idx = tid + it*256;            // 0..1023 float4s
            int r   = idx >> 5;                // 0..31
            int c4  = idx & 31;                // 0..31
            *reinterpret_cast<float4*>(&sB[r][c4*4]) =
                *reinterpret_cast<const float4*>(&W[(size_t)(k0 + r)*HD_ + c4*4]);
        }
        __syncthreads();

        #pragma unroll
        for (int kk = 0; kk < KT; kk++) {
            float4 a  = *reinterpret_cast<const float4*>(&sAT[kk][tr*4]);
            float4 b0 = *reinterpret_cast<const float4*>(&sB[kk][tc*8]);
            float4 b1 = *reinterpret_cast<const float4*>(&sB[kk][tc*8+4]);
            float av[4] = {a.x, a.y, a.z, a.w};
            float bv[8] = {b0.x, b0.y, b0.z, b0.w, b1.x, b1.y, b1.z, b1.w};
            #pragma unroll
            for (int i = 0; i < 4; i++)
                #pragma unroll
                for (int j = 0; j < 8; j++)
                    acc[i][j] += av[i]*bv[j];
        }
        __syncthreads();
    }

    // epilogue: RoPE (Q and K only) + store
    #pragma unroll
    for (int i = 0; i < 4; i++) {
        int m = m0 + tr*4 + i;
        int t = m & (T_ - 1);
        float* orow = &dst[(size_t)m * HD_];
        #pragma unroll
        for (int j = 0; j < 8; j += 2) {
            int col = tc*8 + j;
            float re = acc[i][j], im = acc[i][j+1];
            if (which < 2) {
                int hi = col >> 1;
                float c = rc[t*HALF_ + hi];
                float s = rs[t*HALF_ + hi];
                float r2 = re*c - im*s;
                float i2 = re*s + im*c;
                re = r2; im = i2;
            }
            orow[col]   = re;
            orow[col+1] = im;
        }
    }
}

// ---------------------------------------------------------------------------
// Kernel 2: causal flash attention, fp32 online softmax.
// Grid: (T/BQ, B). 256 threads. BQ=32 query rows, BK=64 key rows per step.
// ---------------------------------------------------------------------------
#define BQ 32
#define BK 64

struct __align__(16) AttnSmem {
    float Q[BQ][HD_];       // pre-scaled
    float KT2[HD_][BK+1];   // K transposed, padded
    float V[BK][HD_];
    float S[BQ][BK+1];      // scores / probs, padded
    float mrow[BQ];
    float lrow[BQ];
    float crow[BQ];
};

__global__ __launch_bounds__(256) void attn_kernel(float* __restrict__ out)
{
    extern __shared__ char smem_raw[];
    AttnSmem& sm = *reinterpret_cast<AttnSmem*>(smem_raw);

    const int b   = blockIdx.y;
    const int qt  = (int)(gridDim.x - 1) - (int)blockIdx.x;  // heavy tiles first
    const int q0  = qt * BQ;
    const int tid = threadIdx.x;

    const float* __restrict__ Qg = g_Q + (size_t)(b*T_)*HD_;
    const float* __restrict__ Kg = g_K + (size_t)(b*T_)*HD_;
    const float* __restrict__ Vg = g_V + (size_t)(b*T_)*HD_;

    const float scale = 0.088388347648318447f;  // 1/sqrt(128)

    // load Q tile (scaled)
    #pragma unroll
    for (int it = 0; it < 4; it++) {
        int idx = tid + it*256;    // 0..1023 float4s (32x32)
        int r   = idx >> 5, c4 = idx & 31;
        float4 v = *reinterpret_cast<const float4*>(
            &Qg[(size_t)(q0 + r)*HD_ + c4*4]);
        v.x *= scale; v.y *= scale; v.z *= scale; v.w *= scale;
        *reinterpret_cast<float4*>(&sm.Q[r][c4*4]) = v;
    }
    if (tid < BQ) { sm.mrow[tid] = -1e30f; sm.lrow[tid] = 0.f; }

    float O[2][8];
    #pragma unroll
    for (int i = 0; i < 2; i++)
        #pragma unroll
        for (int j = 0; j < 8; j++) O[i][j] = 0.f;

    const int sr = tid >> 4;   // 0..15
    const int sc = tid & 15;   // 0..15

    const int nk = (q0 + BQ + BK - 1) / BK;
    for (int kt = 0; kt < nk; kt++) {
        const int k0 = kt * BK;
        __syncthreads();   // protect smem reuse (and Q visibility on iter 0)

        // load K tile transposed
        #pragma unroll
        for (int it = 0; it < 8; it++) {
            int idx = tid + it*256;   // 0..2047 float4s (64x32)
            int r   = idx >> 5, c4 = idx & 31;
            float4 v = *reinterpret_cast<const float4*>(
                &Kg[(size_t)(k0 + r)*HD_ + c4*4]);
            sm.KT2[c4*4+0][r] = v.x;
            sm.KT2[c4*4+1][r] = v.y;
            sm.KT2[c4*4+2][r] = v.z;
            sm.KT2[c4*4+3][r] = v.w;
        }
        // load V tile
        #pragma unroll
        for (int it = 0; it < 8; it++) {
            int idx = tid + it*256;
            int r   = idx >> 5, c4 = idx & 31;
            *reinterpret_cast<float4*>(&sm.V[r][c4*4]) =
                *reinterpret_cast<const float4*>(
                    &Vg[(size_t)(k0 + r)*HD_ + c4*4]);
        }
        __syncthreads();

        // S = Q K^T  (each thread: 2 rows x 4 cols)
        {
            float acc[2][4] = {{0,0,0,0},{0,0,0,0}};
            const int r0 = sr*2, c0 = sc*4;
            #pragma unroll 4
            for (int d = 0; d < HD_; d++) {
                float qa = sm.Q[r0  ][d];
                float qb = sm.Q[r0+1][d];
                #pragma unroll
                for (int j = 0; j < 4; j++) {
                    float kv = sm.KT2[d][c0+j];
                    acc[0][j] += qa*kv;
                    acc[1][j] += qb*kv;
                }
            }
            #pragma unroll
            for (int i = 0; i < 2; i++) {
                int qg = q0 + r0 + i;
                #pragma unroll
                for (int j = 0; j < 4; j++) {
                    int kg = k0 + c0 + j;
                    sm.S[r0+i][c0+j] = (kg <= qg) ? acc[i][j] : -1e9f;
                }
            }
        }
        __syncthreads();

        // online softmax per row (one thread per row)
        if (tid < BQ) {
            int r = tid;
            float mold = sm.mrow[r];
            float mx = mold;
            #pragma unroll 8
            for (int c = 0; c < BK; c++) mx = fmaxf(mx, sm.S[r][c]);
            float corr = __expf(mold - mx);
            float sum = 0.f;
            #pragma unroll 8
            for (int c = 0; c < BK; c++) {
                float p = __expf(sm.S[r][c] - mx);
                sm.S[r][c] = p;
                sum += p;
            }
            sm.mrow[r] = mx;
            sm.lrow[r] = sm.lrow[r]*corr + sum;
            sm.crow[r] = corr;
        }
        __syncthreads();

        // O = O*corr + P @ V  (each thread: 2 rows x 8 cols)
        {
            const int r0 = sr*2, c0 = sc*8;
            float cf0 = sm.crow[r0], cf1 = sm.crow[r0+1];
            #pragma unroll
            for (int j = 0; j < 8; j++) { O[0][j] *= cf0; O[1][j] *= cf1; }
            #pragma unroll 2
            for (int k = 0; k < BK; k++) {
                float p0 = sm.S[r0  ][k];
                float p1 = sm.S[r0+1][k];
                float4 v0 = *reinterpret_cast<const float4*>(&sm.V[k][c0]);
                float4 v1 = *reinterpret_cast<const float4*>(&sm.V[k][c0+4]);
                O[0][0] += p0*v0.x; O[0][1] += p0*v0.y; O[0][2] += p0*v0.z; O[0][3] += p0*v0.w;
                O[0][4] += p0*v1.x; O[0][5] += p0*v1.y; O[0][6] += p0*v1.z; O[0][7] += p0*v1.w;
                O[1][0] += p1*v0.x; O[1][1] += p1*v0.y; O[1][2] += p1*v0.z; O[1][3] += p1*v0.w;
                O[1][4] += p1*v1.x; O[1][5] += p1*v1.y; O[1][6] += p1*v1.z; O[1][7] += p1*v1.w;
            }
        }
    }

    // final normalize + store
    {
        const int r0 = sr*2, c0 = sc*8;
        #pragma unroll
        for (int i = 0; i < 2; i++) {
            float inv = 1.0f / sm.lrow[r0+i];
            float* op = &out[((size_t)(b*T_ + q0 + r0 + i))*HD_ + c0];
            #pragma unroll
            for (int j = 0; j < 8; j++) op[j] = O[i][j]*inv;
        }
    }
}

// ---------------------------------------------------------------------------
extern "C" void kernel_launch(void* const* d_in, const int* in_sizes, int n_in,
                              void* d_out, int out_size)
{
    const float* x  = (const float*)d_in[0];
    const float* Wq = (const float*)d_in[1];
    const float* Wk = (const float*)d_in[2];
    const float* Wv = (const float*)d_in[3];
    const float* rc = (const float*)d_in[4];
    const float* rs = (const float*)d_in[5];
    // d_in[6] (mask) is exactly the causal -1e9 mask; computed analytically.
    float* out = (float*)d_out;

    cudaFuncSetAttribute(attn_kernel,
                         cudaFuncAttributeMaxDynamicSharedMemorySize,
                         (int)sizeof(AttnSmem));

    dim3 g1(MTOT/BM, 3);
    qkv_kernel<<<g1, 256>>>(x, Wq, Wk, Wv, rc, rs);

    dim3 g2(T_/BQ, B_);
    attn_kernel<<<g2, 256, sizeof(AttnSmem)>>>(out);
}

// round 2
// speedup vs baseline: 1.2650x; 1.2650x over previous
#include <cuda_runtime.h>

#define B_    4
#define T_    2048
#define EMB_  2048
#define HD_   128
#define HALF_ 64
#define MTOT  (B_*T_)   // 8192

// Scratch for projected Q/K/V (post-RoPE). 4 MB each.
__device__ float g_Q[MTOT*HD_];
__device__ float g_K[MTOT*HD_];
__device__ float g_V[MTOT*HD_];

// ---------------- packed f32x2 helpers (sm_103a) ----------------
__device__ __forceinline__ unsigned long long f2pack(float lo, float hi) {
    unsigned long long r;
    asm("mov.b64 %0, {%1, %2};" : "=l"(r) : "f"(lo), "f"(hi));
    return r;
}
__device__ __forceinline__ unsigned long long f2dup(float v) { return f2pack(v, v); }
__device__ __forceinline__ void f2unpack(unsigned long long p, float& lo, float& hi) {
    asm("mov.b64 {%0, %1}, %2;" : "=f"(lo), "=f"(hi) : "l"(p));
}
__device__ __forceinline__ unsigned long long f2fma(unsigned long long a,
                                                    unsigned long long b,
                                                    unsigned long long c) {
    unsigned long long d;
    asm("fma.rn.f32x2 %0, %1, %2, %3;" : "=l"(d) : "l"(a), "l"(b), "l"(c));
    return d;
}
__device__ __forceinline__ unsigned long long f2mul(unsigned long long a,
                                                    unsigned long long b) {
    unsigned long long d;
    asm("mul.rn.f32x2 %0, %1, %2;" : "=l"(d) : "l"(a), "l"(b));
    return d;
}

// ---------------------------------------------------------------------------
// Kernel 1: fused QKV projection + RoPE.  BM=64, BN=128(=HD), KT=16.
// 256 threads, 4x8 per thread (packed f32x2 cols), double-buffered smem.
// Grid: (128, 3).
// ---------------------------------------------------------------------------
#define BM 64
#define KT 16
#define NT (EMB_/KT)   // 128

__global__ __launch_bounds__(256, 2) void qkv_kernel(
    const float* __restrict__ x, const float* __restrict__ Wq,
    const float* __restrict__ Wk, const float* __restrict__ Wv,
    const float* __restrict__ rc, const float* __restrict__ rs)
{
    __shared__ float sAT[2][KT][BM+4];   // x tile transposed, padded
    __shared__ float sB [2][KT][HD_];    // W tile

    const int which = blockIdx.y;
    const float* __restrict__ W   = (which==0) ? Wq : ((which==1) ? Wk : Wv);
    float*       __restrict__ dst = (which==0) ? g_Q : ((which==1) ? g_K : g_V);

    const int m0  = blockIdx.x * BM;
    const int tid = threadIdx.x;
    const int tr  = tid >> 4;    // 0..15 -> rows tr*4..+3
    const int tc  = tid & 15;    // 0..15 -> cols tc*8..+7

    // load indices
    const int xr  = tid >> 2;    // 0..63
    const int xc4 = tid & 3;     // 0..3
    const int wr  = tid >> 5;    // 0..7
    const int wc  = tid & 31;    // 0..31
    const float* xp = x + (size_t)(m0 + xr)*EMB_ + xc4*4;
    const float* wp = W + (size_t)wr*HD_ + wc*4;

    // prologue: tile 0
    {
        float4 px  = *(const float4*)(xp);
        float4 pw0 = *(const float4*)(wp);
        float4 pw1 = *(const float4*)(wp + 8*HD_);
        sAT[0][xc4*4+0][xr] = px.x;
        sAT[0][xc4*4+1][xr] = px.y;
        sAT[0][xc4*4+2][xr] = px.z;
        sAT[0][xc4*4+3][xr] = px.w;
        *(float4*)&sB[0][wr  ][wc*4] = pw0;
        *(float4*)&sB[0][wr+8][wc*4] = pw1;
    }
    __syncthreads();

    unsigned long long acc[4][4];
    #pragma unroll
    for (int i = 0; i < 4; i++)
        #pragma unroll
        for (int j = 0; j < 4; j++) acc[i][j] = 0ull;

    for (int t = 0; t < NT; ++t) {
        const int cur = t & 1;
        const bool pre = (t+1 < NT);
        float4 nx, nw0, nw1;
        if (pre) {
            const float* xq = xp + (t+1)*KT;
            const float* wq = wp + (size_t)(t+1)*KT*HD_;
            nx  = *(const float4*)(xq);
            nw0 = *(const float4*)(wq);
            nw1 = *(const float4*)(wq + 8*HD_);
        }

        #pragma unroll
        for (int kk = 0; kk < KT; ++kk) {
            float4 a = *(const float4*)&sAT[cur][kk][tr*4];
            ulonglong2 b01 = *(const ulonglong2*)&sB[cur][kk][tc*8];
            ulonglong2 b23 = *(const ulonglong2*)&sB[cur][kk][tc*8+4];
            unsigned long long a0 = f2dup(a.x), a1 = f2dup(a.y),
                               a2 = f2dup(a.z), a3 = f2dup(a.w);
            acc[0][0]=f2fma(a0,b01.x,acc[0][0]); acc[0][1]=f2fma(a0,b01.y,acc[0][1]);
            acc[0][2]=f2fma(a0,b23.x,acc[0][2]); acc[0][3]=f2fma(a0,b23.y,acc[0][3]);
            acc[1][0]=f2fma(a1,b01.x,acc[1][0]); acc[1][1]=f2fma(a1,b01.y,acc[1][1]);
            acc[1][2]=f2fma(a1,b23.x,acc[1][2]); acc[1][3]=f2fma(a1,b23.y,acc[1][3]);
            acc[2][0]=f2fma(a2,b01.x,acc[2][0]); acc[2][1]=f2fma(a2,b01.y,acc[2][1]);
            acc[2][2]=f2fma(a2,b23.x,acc[2][2]); acc[2][3]=f2fma(a2,b23.y,acc[2][3]);
            acc[3][0]=f2fma(a3,b01.x,acc[3][0]); acc[3][1]=f2fma(a3,b01.y,acc[3][1]);
            acc[3][2]=f2fma(a3,b23.x,acc[3][2]); acc[3][3]=f2fma(a3,b23.y,acc[3][3]);
        }

        if (pre) {
            const int nb = 1-cur;
            sAT[nb][xc4*4+0][xr] = nx.x;
            sAT[nb][xc4*4+1][xr] = nx.y;
            sAT[nb][xc4*4+2][xr] = nx.z;
            sAT[nb][xc4*4+3][xr] = nx.w;
            *(float4*)&sB[nb][wr  ][wc*4] = nw0;
            *(float4*)&sB[nb][wr+8][wc*4] = nw1;
        }
        __syncthreads();
    }

    // epilogue: RoPE (Q,K) + store
    #pragma unroll
    for (int i = 0; i < 4; i++) {
        const int m = m0 + tr*4 + i;
        const int t = m & (T_ - 1);
        float* orow = &dst[(size_t)m * HD_];
        #pragma unroll
        for (int j = 0; j < 4; j++) {
            float re, im;
            f2unpack(acc[i][j], re, im);
            const int col = tc*8 + 2*j;
            if (which < 2) {
                const int hi = tc*4 + j;
                float c = rc[t*HALF_ + hi];
                float s = rs[t*HALF_ + hi];
                float r2 = re*c - im*s;
                float i2 = re*s + im*c;
                re = r2; im = i2;
            }
            *(float2*)&orow[col] = make_float2(re, im);
        }
    }
}

// ---------------------------------------------------------------------------
// Kernel 2: causal flash attention, fp32x2 math, parallel softmax.
// BQ=32, BK=32, 256 threads. smem ~54KB -> 2 blocks/SM.
// bid->(qt,b) mapping pairs heavy tile qt with light tile 63-qt on the same
// SM residue (bid and bid+148 share an SM).
// ---------------------------------------------------------------------------
#define BQ 32
#define BK 32

struct __align__(16) AttnSmem {
    float Q[BQ][132];   // pre-scaled, padded
    float K[BK][132];   // row-major, padded
    float V[BK][HD_];
    float S[BQ][36];
    float mrow[BQ];
    float lrow[BQ];
    float crow[BQ];
};

__global__ __launch_bounds__(256, 2) void attn_kernel(float* __restrict__ out)
{
    extern __shared__ char smem_raw[];
    AttnSmem& sm = *reinterpret_cast<AttnSmem*>(smem_raw);

    // balanced bid -> (qt, b)
    const int bid = blockIdx.x;
    int qt, b;
    if (bid < 108)      { qt = bid >> 2;              b = bid & 3; }
    else if (bid < 148) { int j = bid - 108; qt = 27 + (j >> 2); b = j & 3; }
    else                { int j = bid - 148; qt = 63 - (j >> 2); b = j & 3; }

    const int q0  = qt * BQ;
    const int tid = threadIdx.x;

    const float* __restrict__ Qg = g_Q + (size_t)(b*T_)*HD_;
    const float* __restrict__ Kg = g_K + (size_t)(b*T_)*HD_;
    const float* __restrict__ Vg = g_V + (size_t)(b*T_)*HD_;

    const float scale = 0.088388347648318447f;  // 1/sqrt(128)

    // load Q tile (scaled) into padded smem
    {
        #pragma unroll
        for (int it = 0; it < 4; ++it) {
            int idx = tid + it*256;          // 0..1023 float4s (32x32)
            int r = idx >> 5, c4 = idx & 31;
            float4 v = *(const float4*)&Qg[(size_t)(q0 + r)*HD_ + c4*4];
            v.x *= scale; v.y *= scale; v.z *= scale; v.w *= scale;
            *(float4*)&sm.Q[r][c4*4] = v;
        }
        if (tid < BQ) { sm.mrow[tid] = -1e30f; sm.lrow[tid] = 0.f; }
    }

    // thread maps
    const int r2  = tid >> 4;        // 0..15
    const int cc  = tid & 15;        // 0..15 -> cols {cc, cc+16}
    const int r0s = r2*2;            // S rows r0s, r0s+1
    const int pr0 = r0s;             // PV rows (same map)
    const int pc0 = cc*8;            // PV cols

    unsigned long long Opk[2][4];
    #pragma unroll
    for (int i = 0; i < 2; i++)
        #pragma unroll
        for (int j = 0; j < 4; j++) Opk[i][j] = 0ull;

    const int nk = qt + 1;    // number of BK=32 key tiles (causal)
    for (int kt = 0; kt < nk; ++kt) {
        const int k0 = kt * BK;
        __syncthreads();   // protect smem reuse (and Q/init on iter 0)

        // load K, V tiles
        #pragma unroll
        for (int it = 0; it < 4; ++it) {
            int idx = tid + it*256;   // 0..1023 float4s (32x32)
            int r = idx >> 5, c4 = idx & 31;
            *(float4*)&sm.K[r][c4*4] =
                *(const float4*)&Kg[(size_t)(k0 + r)*HD_ + c4*4];
            *(float4*)&sm.V[r][c4*4] =
                *(const float4*)&Vg[(size_t)(k0 + r)*HD_ + c4*4];
        }
        __syncthreads();

        // S = Q K^T  (dot products in f32x2 pairs; 2 rows x 2 cols per thread)
        {
            unsigned long long s00=0ull, s01=0ull, s10=0ull, s11=0ull;
            const float* qr0 = sm.Q[r0s];
            const float* qr1 = sm.Q[r0s+1];
            const float* kr0 = sm.K[cc];
            const float* kr1 = sm.K[cc+16];
            #pragma unroll 8
            for (int d = 0; d < HD_; d += 4) {
                ulonglong2 qa = *(const ulonglong2*)(qr0 + d);
                ulonglong2 qb = *(const ulonglong2*)(qr1 + d);
                ulonglong2 ka = *(const ulonglong2*)(kr0 + d);
                ulonglong2 kb = *(const ulonglong2*)(kr1 + d);
                s00 = f2fma(qa.x, ka.x, s00); s00 = f2fma(qa.y, ka.y, s00);
                s01 = f2fma(qa.x, kb.x, s01); s01 = f2fma(qa.y, kb.y, s01);
                s10 = f2fma(qb.x, ka.x, s10); s10 = f2fma(qb.y, ka.y, s10);
                s11 = f2fma(qb.x, kb.x, s11); s11 = f2fma(qb.y, kb.y, s11);
            }
            float lo, hi;
            const int qg0 = q0 + r0s, qg1 = qg0 + 1;
            const int kg0 = k0 + cc,  kg1 = k0 + cc + 16;
            f2unpack(s00, lo, hi); sm.S[r0s  ][cc   ] = (kg0<=qg0) ? lo+hi : -1e9f;
            f2unpack(s01, lo, hi); sm.S[r0s  ][cc+16] = (kg1<=qg0) ? lo+hi : -1e9f;
            f2unpack(s10, lo, hi); sm.S[r0s+1][cc   ] = (kg0<=qg1) ? lo+hi : -1e9f;
            f2unpack(s11, lo, hi); sm.S[r0s+1][cc+16] = (kg1<=qg1) ? lo+hi : -1e9f;
        }
        __syncthreads();

        // online softmax: 32 rows x 8 lanes, shuffle reductions
        {
            const int r = tid >> 3, sub = tid & 7;
            float4 sv = *(const float4*)&sm.S[r][sub*4];
            float mold = sm.mrow[r];
            float mx = fmaxf(fmaxf(sv.x, sv.y), fmaxf(sv.z, sv.w));
            mx = fmaxf(mx, mold);
            #pragma unroll
            for (int o = 1; o < 8; o <<= 1)
                mx = fmaxf(mx, __shfl_xor_sync(0xffffffffu, mx, o));
            float e0 = __expf(sv.x - mx), e1 = __expf(sv.y - mx);
            float e2 = __expf(sv.z - mx), e3 = __expf(sv.w - mx);
            float sum = (e0+e1) + (e2+e3);
            #pragma unroll
            for (int o = 1; o < 8; o <<= 1)
                sum += __shfl_xor_sync(0xffffffffu, sum, o);
            *(float4*)&sm.S[r][sub*4] = make_float4(e0, e1, e2, e3);
            if (sub == 0) {
                float corr = __expf(mold - mx);
                sm.crow[r] = corr;
                sm.mrow[r] = mx;
                sm.lrow[r] = sm.lrow[r]*corr + sum;
            }
        }
        __syncthreads();

        // O = O*corr + P @ V   (2 rows x 8 cols, packed)
        {
            unsigned long long cf0 = f2dup(sm.crow[pr0]);
            unsigned long long cf1 = f2dup(sm.crow[pr0+1]);
            #pragma unroll
            for (int j = 0; j < 4; ++j) {
                Opk[0][j] = f2mul(Opk[0][j], cf0);
                Opk[1][j] = f2mul(Opk[1][j], cf1);
            }
            #pragma unroll 4
            for (int k = 0; k < BK; ++k) {
                unsigned long long p0 = f2dup(sm.S[pr0  ][k]);
                unsigned long long p1 = f2dup(sm.S[pr0+1][k]);
                ulonglong2 va = *(const ulonglong2*)&sm.V[k][pc0];
                ulonglong2 vb = *(const ulonglong2*)&sm.V[k][pc0+4];
                Opk[0][0]=f2fma(p0,va.x,Opk[0][0]); Opk[0][1]=f2fma(p0,va.y,Opk[0][1]);
                Opk[0][2]=f2fma(p0,vb.x,Opk[0][2]); Opk[0][3]=f2fma(p0,vb.y,Opk[0][3]);
                Opk[1][0]=f2fma(p1,va.x,Opk[1][0]); Opk[1][1]=f2fma(p1,va.y,Opk[1][1]);
                Opk[1][2]=f2fma(p1,vb.x,Opk[1][2]); Opk[1][3]=f2fma(p1,vb.y,Opk[1][3]);
            }
        }
    }

    // final normalize + store
    {
        #pragma unroll
        for (int i = 0; i < 2; i++) {
            float inv = 1.0f / sm.lrow[pr0 + i];
            float* op = &out[((size_t)(b*T_ + q0 + pr0 + i))*HD_ + pc0];
            #pragma unroll
            for (int j = 0; j < 4; j++) {
                float lo, hi;
                f2unpack(Opk[i][j], lo, hi);
                *(float2*)&op[2*j] = make_float2(lo*inv, hi*inv);
            }
        }
    }
}

// ---------------------------------------------------------------------------
extern "C" void kernel_launch(void* const* d_in, const int* in_sizes, int n_in,
                              void* d_out, int out_size)
{
    const float* x  = (const float*)d_in[0];
    const float* Wq = (const float*)d_in[1];
    const float* Wk = (const float*)d_in[2];
    const float* Wv = (const float*)d_in[3];
    const float* rc = (const float*)d_in[4];
    const float* rs = (const float*)d_in[5];
    // d_in[6] (mask) is exactly the causal -1e9 mask; computed analytically.
    float* out = (float*)d_out;

    cudaFuncSetAttribute(attn_kernel,
                         cudaFuncAttributeMaxDynamicSharedMemorySize,
                         (int)sizeof(AttnSmem));

    dim3 g1(MTOT/BM, 3);
    qkv_kernel<<<g1, 256>>>(x, Wq, Wk, Wv, rc, rs);

    attn_kernel<<<256, 256, sizeof(AttnSmem)>>>(out);
}

// round 4
// speedup vs baseline: 2.2441x; 1.7740x over previous
#include <cuda_runtime.h>

#define B_    4
#define T_    2048
#define EMB_  2048
#define HD_   128
#define HALF_ 64
#define MTOT  (B_*T_)   // 8192

// Scratch for projected Q/K/V (post-RoPE). 4 MB each.
__device__ float g_Q[MTOT*HD_];
__device__ float g_K[MTOT*HD_];
__device__ float g_V[MTOT*HD_];

// ---------------- packed f32x2 helpers (sm_103a) ----------------
__device__ __forceinline__ unsigned long long f2pack(float lo, float hi) {
    unsigned long long r;
    asm("mov.b64 %0, {%1, %2};" : "=l"(r) : "f"(lo), "f"(hi));
    return r;
}
__device__ __forceinline__ unsigned long long f2dup(float v) { return f2pack(v, v); }
__device__ __forceinline__ void f2unpack(unsigned long long p, float& lo, float& hi) {
    asm("mov.b64 {%0, %1}, %2;" : "=f"(lo), "=f"(hi) : "l"(p));
}
__device__ __forceinline__ unsigned long long f2fma(unsigned long long a,
                                                    unsigned long long b,
                                                    unsigned long long c) {
    unsigned long long d;
    asm("fma.rn.f32x2 %0, %1, %2, %3;" : "=l"(d) : "l"(a), "l"(b), "l"(c));
    return d;
}
__device__ __forceinline__ unsigned long long f2mul(unsigned long long a,
                                                    unsigned long long b) {
    unsigned long long d;
    asm("mul.rn.f32x2 %0, %1, %2;" : "=l"(d) : "l"(a), "l"(b));
    return d;
}

// ---------------- tf32 mma helpers ----------------
__device__ __forceinline__ float4 cvt_tf32_4(float4 v) {
    asm("cvt.rna.tf32.f32 %0, %0;\n\t"
        "cvt.rna.tf32.f32 %1, %1;\n\t"
        "cvt.rna.tf32.f32 %2, %2;\n\t"
        "cvt.rna.tf32.f32 %3, %3;"
        : "+f"(v.x), "+f"(v.y), "+f"(v.z), "+f"(v.w));
    return v;
}
__device__ __forceinline__ void mma_tf32(float c[4], const unsigned a[4],
                                         const unsigned b[2]) {
    asm("mma.sync.aligned.m16n8k8.row.col.f32.tf32.tf32.f32 "
        "{%0,%1,%2,%3},{%4,%5,%6,%7},{%8,%9},{%0,%1,%2,%3};"
        : "+f"(c[0]), "+f"(c[1]), "+f"(c[2]), "+f"(c[3])
        : "r"(a[0]), "r"(a[1]), "r"(a[2]), "r"(a[3]),
          "r"(b[0]), "r"(b[1]));
}

// ---------------------------------------------------------------------------
// Kernel 1: fused QKV projection + RoPE via tensor-core tf32 mma.
// BM=64, BN=128(=HD), BK=32. 256 threads, warp tile 32x32.
// Grid: (128, 3). Double-buffered smem, register prefetch.
// smem strides: A row=36 floats, B row=132 floats -> conflict-free frag LDS.
// ---------------------------------------------------------------------------
#define QBM 64
#define QBK 32

struct __align__(16) QkvSmem {
    float A[2][QBM][QBK+4];   // 64 x 36
    float B[2][QBK][132];     // 32 x 132
};

__global__ __launch_bounds__(256) void qkv_kernel(
    const float* __restrict__ x, const float* __restrict__ Wq,
    const float* __restrict__ Wk, const float* __restrict__ Wv,
    const float* __restrict__ rc, const float* __restrict__ rs)
{
    extern __shared__ char smem_raw[];
    QkvSmem& sm = *reinterpret_cast<QkvSmem*>(smem_raw);

    const int which = blockIdx.y;
    const float* __restrict__ W   = (which==0) ? Wq : ((which==1) ? Wk : Wv);
    float*       __restrict__ dst = (which==0) ? g_Q : ((which==1) ? g_K : g_V);

    const int m0   = blockIdx.x * QBM;
    const int tid  = threadIdx.x;
    const int lane = tid & 31;
    const int wid  = tid >> 5;
    const int wm   = wid & 1;      // warp rows: wm*32 .. +31
    const int wn   = wid >> 1;     // warp cols: wn*32 .. +31
    const int g    = lane >> 2;    // 0..7
    const int tg   = lane & 3;     // 0..3

    // global load indices
    const int ar  = tid >> 3;          // 0..31 -> rows {ar, ar+32}
    const int ac4 = tid & 7;           // col ac4*4
    const float* xp = x + (size_t)(m0 + ar)*EMB_ + ac4*4;
    const int br  = wid;               // 0..7 -> rows {br, br+8, br+16, br+24}
    const int bc4 = lane;              // col bc4*4
    const float* wp = W + (size_t)br*HD_ + bc4*4;

    // prologue: tile 0
    {
        float4 a0 = cvt_tf32_4(*(const float4*)(xp));
        float4 a1 = cvt_tf32_4(*(const float4*)(xp + (size_t)32*EMB_));
        *(float4*)&sm.A[0][ar   ][ac4*4] = a0;
        *(float4*)&sm.A[0][ar+32][ac4*4] = a1;
        #pragma unroll
        for (int i = 0; i < 4; i++) {
            float4 bv = cvt_tf32_4(*(const float4*)(wp + (size_t)i*8*HD_));
            *(float4*)&sm.B[0][br + i*8][bc4*4] = bv;
        }
    }
    __syncthreads();

    float acc[2][4][4];
    #pragma unroll
    for (int mf = 0; mf < 2; mf++)
        #pragma unroll
        for (int nf = 0; nf < 4; nf++)
            #pragma unroll
            for (int r = 0; r < 4; r++) acc[mf][nf][r] = 0.f;

    const int NTILES = EMB_ / QBK;   // 64
    for (int t = 0; t < NTILES; ++t) {
        const int cur = t & 1;
        const bool pre = (t + 1 < NTILES);
        float4 na0, na1, nb[4];
        if (pre) {
            const float* xq = xp + (t+1)*QBK;
            const float* wq = wp + (size_t)(t+1)*QBK*HD_;
            na0 = cvt_tf32_4(*(const float4*)(xq));
            na1 = cvt_tf32_4(*(const float4*)(xq + (size_t)32*EMB_));
            #pragma unroll
            for (int i = 0; i < 4; i++)
                nb[i] = cvt_tf32_4(*(const float4*)(wq + (size_t)i*8*HD_));
        }

        const float (*As)[QBK+4] = sm.A[cur];
        const float (*Bs)[132]   = sm.B[cur];
        #pragma unroll
        for (int ks = 0; ks < 4; ++ks) {
            const int k0 = ks*8;
            unsigned a[2][4], b[4][2];
            #pragma unroll
            for (int mf = 0; mf < 2; mf++) {
                const int r = wm*32 + mf*16 + g;
                a[mf][0] = __float_as_uint(As[r  ][k0+tg]);
                a[mf][1] = __float_as_uint(As[r+8][k0+tg]);
                a[mf][2] = __float_as_uint(As[r  ][k0+tg+4]);
                a[mf][3] = __float_as_uint(As[r+8][k0+tg+4]);
            }
            #pragma unroll
            for (int nf = 0; nf < 4; nf++) {
                const int n = wn*32 + nf*8 + g;
                b[nf][0] = __float_as_uint(Bs[k0+tg  ][n]);
                b[nf][1] = __float_as_uint(Bs[k0+tg+4][n]);
            }
            #pragma unroll
            for (int mf = 0; mf < 2; mf++)
                #pragma unroll
                for (int nf = 0; nf < 4; nf++)
                    mma_tf32(acc[mf][nf], a[mf], b[nf]);
        }

        if (pre) {
            const int nbuf = 1 - cur;
            *(float4*)&sm.A[nbuf][ar   ][ac4*4] = na0;
            *(float4*)&sm.A[nbuf][ar+32][ac4*4] = na1;
            #pragma unroll
            for (int i = 0; i < 4; i++)
                *(float4*)&sm.B[nbuf][br + i*8][bc4*4] = nb[i];
        }
        __syncthreads();
    }

    // epilogue: RoPE (Q,K) + store. (c0,c1) and (c2,c3) are adjacent
    // (re,im) column pairs: col = wn*32 + nf*8 + 2*tg.
    #pragma unroll
    for (int mf = 0; mf < 2; mf++) {
        const int row0 = m0 + wm*32 + mf*16 + g;
        const int row1 = row0 + 8;
        const int t0 = row0 & (T_ - 1);
        const int t1 = row1 & (T_ - 1);
        #pragma unroll
        for (int nf = 0; nf < 4; nf++) {
            const int col = wn*32 + nf*8 + 2*tg;
            const int hi  = col >> 1;
            float re0 = acc[mf][nf][0], im0 = acc[mf][nf][1];
            float re1 = acc[mf][nf][2], im1 = acc[mf][nf][3];
            if (which < 2) {
                float c0 = rc[t0*HALF_ + hi], s0 = rs[t0*HALF_ + hi];
                float c1 = rc[t1*HALF_ + hi], s1 = rs[t1*HALF_ + hi];
                float r2, i2;
                r2 = re0*c0 - im0*s0; i2 = re0*s0 + im0*c0; re0 = r2; im0 = i2;
                r2 = re1*c1 - im1*s1; i2 = re1*s1 + im1*c1; re1 = r2; im1 = i2;
            }
            *(float2*)&dst[(size_t)row0*HD_ + col] = make_float2(re0, im0);
            *(float2*)&dst[(size_t)row1*HD_ + col] = make_float2(re1, im1);
        }
    }
}

// ---------------------------------------------------------------------------
// Kernel 2: causal flash attention, fp32x2 math, parallel softmax.
// BQ=32, BK=32, 256 threads. (unchanged from R2)
// ---------------------------------------------------------------------------
#define BQ 32
#define BK 32

struct __align__(16) AttnSmem {
    float Q[BQ][132];   // pre-scaled, padded
    float K[BK][132];   // row-major, padded
    float V[BK][HD_];
    float S[BQ][36];
    float mrow[BQ];
    float lrow[BQ];
    float crow[BQ];
};

__global__ __launch_bounds__(256, 2) void attn_kernel(float* __restrict__ out)
{
    extern __shared__ char smem_raw[];
    AttnSmem& sm = *reinterpret_cast<AttnSmem*>(smem_raw);

    // balanced bid -> (qt, b)
    const int bid = blockIdx.x;
    int qt, b;
    if (bid < 108)      { qt = bid >> 2;              b = bid & 3; }
    else if (bid < 148) { int j = bid - 108; qt = 27 + (j >> 2); b = j & 3; }
    else                { int j = bid - 148; qt = 63 - (j >> 2); b = j & 3; }

    const int q0  = qt * BQ;
    const int tid = threadIdx.x;

    const float* __restrict__ Qg = g_Q + (size_t)(b*T_)*HD_;
    const float* __restrict__ Kg = g_K + (size_t)(b*T_)*HD_;
    const float* __restrict__ Vg = g_V + (size_t)(b*T_)*HD_;

    const float scale = 0.088388347648318447f;  // 1/sqrt(128)

    // load Q tile (scaled) into padded smem
    {
        #pragma unroll
        for (int it = 0; it < 4; ++it) {
            int idx = tid + it*256;          // 0..1023 float4s (32x32)
            int r = idx >> 5, c4 = idx & 31;
            float4 v = *(const float4*)&Qg[(size_t)(q0 + r)*HD_ + c4*4];
            v.x *= scale; v.y *= scale; v.z *= scale; v.w *= scale;
            *(float4*)&sm.Q[r][c4*4] = v;
        }
        if (tid < BQ) { sm.mrow[tid] = -1e30f; sm.lrow[tid] = 0.f; }
    }

    // thread maps
    const int r2  = tid >> 4;        // 0..15
    const int cc  = tid & 15;        // 0..15 -> cols {cc, cc+16}
    const int r0s = r2*2;            // S rows r0s, r0s+1
    const int pr0 = r0s;             // PV rows (same map)
    const int pc0 = cc*8;            // PV cols

    unsigned long long Opk[2][4];
    #pragma unroll
    for (int i = 0; i < 2; i++)
        #pragma unroll
        for (int j = 0; j < 4; j++) Opk[i][j] = 0ull;

    const int nk = qt + 1;    // number of BK=32 key tiles (causal)
    for (int kt = 0; kt < nk; ++kt) {
        const int k0 = kt * BK;
        __syncthreads();   // protect smem reuse (and Q/init on iter 0)

        // load K, V tiles
        #pragma unroll
        for (int it = 0; it < 4; ++it) {
            int idx = tid + it*256;   // 0..1023 float4s (32x32)
            int r = idx >> 5, c4 = idx & 31;
            *(float4*)&sm.K[r][c4*4] =
                *(const float4*)&Kg[(size_t)(k0 + r)*HD_ + c4*4];
            *(float4*)&sm.V[r][c4*4] =
                *(const float4*)&Vg[(size_t)(k0 + r)*HD_ + c4*4];
        }
        __syncthreads();

        // S = Q K^T  (dot products in f32x2 pairs; 2 rows x 2 cols per thread)
        {
            unsigned long long s00=0ull, s01=0ull, s10=0ull, s11=0ull;
            const float* qr0 = sm.Q[r0s];
            const float* qr1 = sm.Q[r0s+1];
            const float* kr0 = sm.K[cc];
            const float* kr1 = sm.K[cc+16];
            #pragma unroll 8
            for (int d = 0; d < HD_; d += 4) {
                ulonglong2 qa = *(const ulonglong2*)(qr0 + d);
                ulonglong2 qb = *(const ulonglong2*)(qr1 + d);
                ulonglong2 ka = *(const ulonglong2*)(kr0 + d);
                ulonglong2 kb = *(const ulonglong2*)(kr1 + d);
                s00 = f2fma(qa.x, ka.x, s00); s00 = f2fma(qa.y, ka.y, s00);
                s01 = f2fma(qa.x, kb.x, s01); s01 = f2fma(qa.y, kb.y, s01);
                s10 = f2fma(qb.x, ka.x, s10); s10 = f2fma(qb.y, ka.y, s10);
                s11 = f2fma(qb.x, kb.x, s11); s11 = f2fma(qb.y, kb.y, s11);
            }
            float lo, hi;
            const int qg0 = q0 + r0s, qg1 = qg0 + 1;
            const int kg0 = k0 + cc,  kg1 = k0 + cc + 16;
            f2unpack(s00, lo, hi); sm.S[r0s  ][cc   ] = (kg0<=qg0) ? lo+hi : -1e9f;
            f2unpack(s01, lo, hi); sm.S[r0s  ][cc+16] = (kg1<=qg0) ? lo+hi : -1e9f;
            f2unpack(s10, lo, hi); sm.S[r0s+1][cc   ] = (kg0<=qg1) ? lo+hi : -1e9f;
            f2unpack(s11, lo, hi); sm.S[r0s+1][cc+16] = (kg1<=qg1) ? lo+hi : -1e9f;
        }
        __syncthreads();

        // online softmax: 32 rows x 8 lanes, shuffle reductions
        {
            const int r = tid >> 3, sub = tid & 7;
            float4 sv = *(const float4*)&sm.S[r][sub*4];
            float mold = sm.mrow[r];
            float mx = fmaxf(fmaxf(sv.x, sv.y), fmaxf(sv.z, sv.w));
            mx = fmaxf(mx, mold);
            #pragma unroll
            for (int o = 1; o < 8; o <<= 1)
                mx = fmaxf(mx, __shfl_xor_sync(0xffffffffu, mx, o));
            float e0 = __expf(sv.x - mx), e1 = __expf(sv.y - mx);
            float e2 = __expf(sv.z - mx), e3 = __expf(sv.w - mx);
            float sum = (e0+e1) + (e2+e3);
            #pragma unroll
            for (int o = 1; o < 8; o <<= 1)
                sum += __shfl_xor_sync(0xffffffffu, sum, o);
            *(float4*)&sm.S[r][sub*4] = make_float4(e0, e1, e2, e3);
            if (sub == 0) {
                float corr = __expf(mold - mx);
                sm.crow[r] = corr;
                sm.mrow[r] = mx;
                sm.lrow[r] = sm.lrow[r]*corr + sum;
            }
        }
        __syncthreads();

        // O = O*corr + P @ V   (2 rows x 8 cols, packed)
        {
            unsigned long long cf0 = f2dup(sm.crow[pr0]);
            unsigned long long cf1 = f2dup(sm.crow[pr0+1]);
            #pragma unroll
            for (int j = 0; j < 4; ++j) {
                Opk[0][j] = f2mul(Opk[0][j], cf0);
                Opk[1][j] = f2mul(Opk[1][j], cf1);
            }
            #pragma unroll 4
            for (int k = 0; k < BK; ++k) {
                unsigned long long p0 = f2dup(sm.S[pr0  ][k]);
                unsigned long long p1 = f2dup(sm.S[pr0+1][k]);
                ulonglong2 va = *(const ulonglong2*)&sm.V[k][pc0];
                ulonglong2 vb = *(const ulonglong2*)&sm.V[k][pc0+4];
                Opk[0][0]=f2fma(p0,va.x,Opk[0][0]); Opk[0][1]=f2fma(p0,va.y,Opk[0][1]);
                Opk[0][2]=f2fma(p0,vb.x,Opk[0][2]); Opk[0][3]=f2fma(p0,vb.y,Opk[0][3]);
                Opk[1][0]=f2fma(p1,va.x,Opk[1][0]); Opk[1][1]=f2fma(p1,va.y,Opk[1][1]);
                Opk[1][2]=f2fma(p1,vb.x,Opk[1][2]); Opk[1][3]=f2fma(p1,vb.y,Opk[1][3]);
            }
        }
    }

    // final normalize + store
    {
        #pragma unroll
        for (int i = 0; i < 2; i++) {
            float inv = 1.0f / sm.lrow[pr0 + i];
            float* op = &out[((size_t)(b*T_ + q0 + pr0 + i))*HD_ + pc0];
            #pragma unroll
            for (int j = 0; j < 4; j++) {
                float lo, hi;
                f2unpack(Opk[i][j], lo, hi);
                *(float2*)&op[2*j] = make_float2(lo*inv, hi*inv);
            }
        }
    }
}

// ---------------------------------------------------------------------------
extern "C" void kernel_launch(void* const* d_in, const int* in_sizes, int n_in,
                              void* d_out, int out_size)
{
    const float* x  = (const float*)d_in[0];
    const float* Wq = (const float*)d_in[1];
    const float* Wk = (const float*)d_in[2];
    const float* Wv = (const float*)d_in[3];
    const float* rc = (const float*)d_in[4];
    const float* rs = (const float*)d_in[5];
    // d_in[6] (mask) is exactly the causal -1e9 mask; computed analytically.
    float* out = (float*)d_out;

    cudaFuncSetAttribute(qkv_kernel,
                         cudaFuncAttributeMaxDynamicSharedMemorySize,
                         (int)sizeof(QkvSmem));
    cudaFuncSetAttribute(attn_kernel,
                         cudaFuncAttributeMaxDynamicSharedMemorySize,
                         (int)sizeof(AttnSmem));

    dim3 g1(MTOT/QBM, 3);
    qkv_kernel<<<g1, 256, sizeof(QkvSmem)>>>(x, Wq, Wk, Wv, rc, rs);

    attn_kernel<<<256, 256, sizeof(AttnSmem)>>>(out);
}

// round 5
// speedup vs baseline: 3.9678x; 1.7681x over previous
#include <cuda_runtime.h>

#define B_    4
#define T_    2048
#define EMB_  2048
#define HD_   128
#define HALF_ 64
#define MTOT  (B_*T_)   // 8192

// Scratch for projected Q/K/V (post-RoPE, tf32-rounded; Q pre-scaled). 4 MB each.
__device__ float g_Q[MTOT*HD_];
__device__ float g_K[MTOT*HD_];
__device__ float g_V[MTOT*HD_];

// ---------------- tf32 mma helpers ----------------
__device__ __forceinline__ float cvt1_tf32(float v) {
    asm("cvt.rna.tf32.f32 %0, %0;" : "+f"(v));
    return v;
}
__device__ __forceinline__ float4 cvt_tf32_4(float4 v) {
    asm("cvt.rna.tf32.f32 %0, %0;\n\t"
        "cvt.rna.tf32.f32 %1, %1;\n\t"
        "cvt.rna.tf32.f32 %2, %2;\n\t"
        "cvt.rna.tf32.f32 %3, %3;"
        : "+f"(v.x), "+f"(v.y), "+f"(v.z), "+f"(v.w));
    return v;
}
__device__ __forceinline__ void mma_tf32(float c[4], const unsigned a[4],
                                         const unsigned b[2]) {
    asm("mma.sync.aligned.m16n8k8.row.col.f32.tf32.tf32.f32 "
        "{%0,%1,%2,%3},{%4,%5,%6,%7},{%8,%9},{%0,%1,%2,%3};"
        : "+f"(c[0]), "+f"(c[1]), "+f"(c[2]), "+f"(c[3])
        : "r"(a[0]), "r"(a[1]), "r"(a[2]), "r"(a[3]),
          "r"(b[0]), "r"(b[1]));
}

// ---------------- cp.async helpers ----------------
__device__ __forceinline__ unsigned smem_u32(const void* p) {
    return (unsigned)__cvta_generic_to_shared(p);
}
__device__ __forceinline__ void cp16(unsigned dst, const void* src) {
    asm volatile("cp.async.ca.shared.global [%0], [%1], 16;"
                 :: "r"(dst), "l"(src));
}
__device__ __forceinline__ void cp_commit() {
    asm volatile("cp.async.commit_group;");
}
__device__ __forceinline__ void cp_wait0() {
    asm volatile("cp.async.wait_group 0;");
}

// ---------------------------------------------------------------------------
// Kernel 1: fused QKV projection + RoPE via tf32 mma.
// BM=64, BN=128(=HD), BK=32. 256 threads, warp tile 32x32. Grid: (128, 3).
// Epilogue: RoPE (Q,K), Q pre-scaled by 1/sqrt(HD), ALL outputs tf32-rounded.
// ---------------------------------------------------------------------------
#define QBM 64
#define QBK 32

struct __align__(16) QkvSmem {
    float A[2][QBM][QBK+4];   // 64 x 36
    float B[2][QBK][132];     // 32 x 132
};

__global__ __launch_bounds__(256) void qkv_kernel(
    const float* __restrict__ x, const float* __restrict__ Wq,
    const float* __restrict__ Wk, const float* __restrict__ Wv,
    const float* __restrict__ rc, const float* __restrict__ rs)
{
    extern __shared__ char smem_raw[];
    QkvSmem& sm = *reinterpret_cast<QkvSmem*>(smem_raw);

    const int which = blockIdx.y;
    const float* __restrict__ W   = (which==0) ? Wq : ((which==1) ? Wk : Wv);
    float*       __restrict__ dst = (which==0) ? g_Q : ((which==1) ? g_K : g_V);

    const int m0   = blockIdx.x * QBM;
    const int tid  = threadIdx.x;
    const int lane = tid & 31;
    const int wid  = tid >> 5;
    const int wm   = wid & 1;      // warp rows: wm*32 .. +31
    const int wn   = wid >> 1;     // warp cols: wn*32 .. +31
    const int g    = lane >> 2;    // 0..7
    const int tg   = lane & 3;     // 0..3

    // global load indices
    const int ar  = tid >> 3;          // 0..31 -> rows {ar, ar+32}
    const int ac4 = tid & 7;           // col ac4*4
    const float* xp = x + (size_t)(m0 + ar)*EMB_ + ac4*4;
    const int br  = wid;               // 0..7 -> rows {br, br+8, br+16, br+24}
    const int bc4 = lane;              // col bc4*4
    const float* wp = W + (size_t)br*HD_ + bc4*4;

    // prologue: tile 0
    {
        float4 a0 = cvt_tf32_4(*(const float4*)(xp));
        float4 a1 = cvt_tf32_4(*(const float4*)(xp + (size_t)32*EMB_));
        *(float4*)&sm.A[0][ar   ][ac4*4] = a0;
        *(float4*)&sm.A[0][ar+32][ac4*4] = a1;
        #pragma unroll
        for (int i = 0; i < 4; i++) {
            float4 bv = cvt_tf32_4(*(const float4*)(wp + (size_t)i*8*HD_));
            *(float4*)&sm.B[0][br + i*8][bc4*4] = bv;
        }
    }
    __syncthreads();

    float acc[2][4][4];
    #pragma unroll
    for (int mf = 0; mf < 2; mf++)
        #pragma unroll
        for (int nf = 0; nf < 4; nf++)
            #pragma unroll
            for (int r = 0; r < 4; r++) acc[mf][nf][r] = 0.f;

    const int NTILES = EMB_ / QBK;   // 64
    for (int t = 0; t < NTILES; ++t) {
        const int cur = t & 1;
        const bool pre = (t + 1 < NTILES);
        float4 na0, na1, nb[4];
        if (pre) {
            const float* xq = xp + (t+1)*QBK;
            const float* wq = wp + (size_t)(t+1)*QBK*HD_;
            na0 = cvt_tf32_4(*(const float4*)(xq));
            na1 = cvt_tf32_4(*(const float4*)(xq + (size_t)32*EMB_));
            #pragma unroll
            for (int i = 0; i < 4; i++)
                nb[i] = cvt_tf32_4(*(const float4*)(wq + (size_t)i*8*HD_));
        }

        const float (*As)[QBK+4] = sm.A[cur];
        const float (*Bs)[132]   = sm.B[cur];
        #pragma unroll
        for (int ks = 0; ks < 4; ++ks) {
            const int k0 = ks*8;
            unsigned a[2][4], b[4][2];
            #pragma unroll
            for (int mf = 0; mf < 2; mf++) {
                const int r = wm*32 + mf*16 + g;
                a[mf][0] = __float_as_uint(As[r  ][k0+tg]);
                a[mf][1] = __float_as_uint(As[r+8][k0+tg]);
                a[mf][2] = __float_as_uint(As[r  ][k0+tg+4]);
                a[mf][3] = __float_as_uint(As[r+8][k0+tg+4]);
            }
            #pragma unroll
            for (int nf = 0; nf < 4; nf++) {
                const int n = wn*32 + nf*8 + g;
                b[nf][0] = __float_as_uint(Bs[k0+tg  ][n]);
                b[nf][1] = __float_as_uint(Bs[k0+tg+4][n]);
            }
            #pragma unroll
            for (int mf = 0; mf < 2; mf++)
                #pragma unroll
                for (int nf = 0; nf < 4; nf++)
                    mma_tf32(acc[mf][nf], a[mf], b[nf]);
        }

        if (pre) {
            const int nbuf = 1 - cur;
            *(float4*)&sm.A[nbuf][ar   ][ac4*4] = na0;
            *(float4*)&sm.A[nbuf][ar+32][ac4*4] = na1;
            #pragma unroll
            for (int i = 0; i < 4; i++)
                *(float4*)&sm.B[nbuf][br + i*8][bc4*4] = nb[i];
        }
        __syncthreads();
    }

    // epilogue: RoPE (Q,K), Q scale, tf32 round, store
    const float qscale = 0.088388347648318447f;  // 1/sqrt(128)
    #pragma unroll
    for (int mf = 0; mf < 2; mf++) {
        const int row0 = m0 + wm*32 + mf*16 + g;
        const int row1 = row0 + 8;
        const int t0 = row0 & (T_ - 1);
        const int t1 = row1 & (T_ - 1);
        #pragma unroll
        for (int nf = 0; nf < 4; nf++) {
            const int col = wn*32 + nf*8 + 2*tg;
            const int hi  = col >> 1;
            float re0 = acc[mf][nf][0], im0 = acc[mf][nf][1];
            float re1 = acc[mf][nf][2], im1 = acc[mf][nf][3];
            if (which < 2) {
                float c0 = rc[t0*HALF_ + hi], s0 = rs[t0*HALF_ + hi];
                float c1 = rc[t1*HALF_ + hi], s1 = rs[t1*HALF_ + hi];
                float r2, i2;
                r2 = re0*c0 - im0*s0; i2 = re0*s0 + im0*c0; re0 = r2; im0 = i2;
                r2 = re1*c1 - im1*s1; i2 = re1*s1 + im1*c1; re1 = r2; im1 = i2;
            }
            if (which == 0) { re0 *= qscale; im0 *= qscale; re1 *= qscale; im1 *= qscale; }
            re0 = cvt1_tf32(re0); im0 = cvt1_tf32(im0);
            re1 = cvt1_tf32(re1); im1 = cvt1_tf32(im1);
            *(float2*)&dst[(size_t)row0*HD_ + col] = make_float2(re0, im0);
            *(float2*)&dst[(size_t)row1*HD_ + col] = make_float2(re1, im1);
        }
    }
}

// ---------------------------------------------------------------------------
// Kernel 2: causal flash attention on the tensor pipe (tf32 mma).
// BQ=32, BK=32, 256 threads (8 warps).
// S-phase:  warp (wm=wid&1, wn=wid>>1) owns S[wm*16..+15][wn*8..+7], K=128.
// PV-phase: warp owns O[wm*16..+15][wn*32..+31], K=32.
// smem strides chosen conflict-free: Q/K=132, V=136, S/P=36.
// ---------------------------------------------------------------------------
#define BQ 32
#define BK 32

struct __align__(16) AttnSmem {
    float Q[BQ][132];
    float K[BK][132];
    float V[BK][136];
    float S[BQ][36];     // scores, then P (tf32-rounded)
    float mrow[BQ];
    float lrow[BQ];
    float crow[BQ];
};

__global__ __launch_bounds__(256, 3) void attn_kernel(float* __restrict__ out)
{
    extern __shared__ char smem_raw[];
    AttnSmem& sm = *reinterpret_cast<AttnSmem*>(smem_raw);

    // balanced bid -> (qt, b): pairs heavy with light on same SM residue
    const int bid = blockIdx.x;
    int qt, b;
    if (bid < 108)      { qt = bid >> 2;              b = bid & 3; }
    else if (bid < 148) { int j = bid - 108; qt = 27 + (j >> 2); b = j & 3; }
    else                { int j = bid - 148; qt = 63 - (j >> 2); b = j & 3; }

    const int q0   = qt * BQ;
    const int tid  = threadIdx.x;
    const int lane = tid & 31;
    const int wid  = tid >> 5;
    const int g    = lane >> 2;    // 0..7
    const int tg   = lane & 3;     // 0..3
    const int wm   = wid & 1;      // m-half (rows wm*16..+15)
    const int wn   = wid >> 1;     // 0..3

    const float* __restrict__ Qg = g_Q + (size_t)(b*T_)*HD_;
    const float* __restrict__ Kg = g_K + (size_t)(b*T_)*HD_;
    const float* __restrict__ Vg = g_V + (size_t)(b*T_)*HD_;

    // async-load Q tile (already scaled + tf32-rounded by qkv kernel)
    const int lr  = tid >> 3;          // 0..31
    const int lcf = (tid & 7) * 16;    // float col 0..112
    {
        const float* src = Qg + (size_t)(q0 + lr)*HD_ + lcf;
        unsigned dstq = smem_u32(&sm.Q[lr][lcf]);
        #pragma unroll
        for (int i = 0; i < 4; i++) cp16(dstq + i*16, src + i*4);
        cp_commit();
    }
    if (tid < BQ) { sm.mrow[tid] = -1e30f; sm.lrow[tid] = 0.f; }

    float O[4][4];
    #pragma unroll
    for (int nf = 0; nf < 4; nf++)
        #pragma unroll
        for (int r = 0; r < 4; r++) O[nf][r] = 0.f;

    const int nk = qt + 1;
    for (int kt = 0; kt < nk; ++kt) {
        const int k0 = kt * BK;
        __syncthreads();   // prev iter done with K/V/S

        // async-load K, V tiles
        {
            const float* srck = Kg + (size_t)(k0 + lr)*HD_ + lcf;
            const float* srcv = Vg + (size_t)(k0 + lr)*HD_ + lcf;
            unsigned dstk = smem_u32(&sm.K[lr][lcf]);
            unsigned dstv = smem_u32(&sm.V[lr][lcf]);
            #pragma unroll
            for (int i = 0; i < 4; i++) cp16(dstk + i*16, srck + i*4);
            #pragma unroll
            for (int i = 0; i < 4; i++) cp16(dstv + i*16, srcv + i*4);
            cp_commit();
            cp_wait0();
        }
        __syncthreads();

        // ---- S = Q K^T on tensor pipe ----
        {
            float sacc[4] = {0.f, 0.f, 0.f, 0.f};
            const int ar0 = wm*16 + g;
            const int bn  = wn*8 + g;     // key row in tile
            #pragma unroll
            for (int ks = 0; ks < 16; ks++) {
                const int kk = ks*8;
                unsigned a[4], bb[2];
                a[0] = __float_as_uint(sm.Q[ar0  ][kk+tg]);
                a[1] = __float_as_uint(sm.Q[ar0+8][kk+tg]);
                a[2] = __float_as_uint(sm.Q[ar0  ][kk+tg+4]);
                a[3] = __float_as_uint(sm.Q[ar0+8][kk+tg+4]);
                bb[0] = __float_as_uint(sm.K[bn][kk+tg]);
                bb[1] = __float_as_uint(sm.K[bn][kk+tg+4]);
                mma_tf32(sacc, a, bb);
            }
            // causal mask + write scores
            const int qg0 = q0 + ar0, qg1 = qg0 + 8;
            const int c   = wn*8 + 2*tg;
            const int kg  = k0 + c;
            sm.S[ar0  ][c  ] = (kg   <= qg0) ? sacc[0] : -1e9f;
            sm.S[ar0  ][c+1] = (kg+1 <= qg0) ? sacc[1] : -1e9f;
            sm.S[ar0+8][c  ] = (kg   <= qg1) ? sacc[2] : -1e9f;
            sm.S[ar0+8][c+1] = (kg+1 <= qg1) ? sacc[3] : -1e9f;
        }
        __syncthreads();

        // ---- online softmax: 32 rows x 8 lanes ----
        {
            const int r = tid >> 3, sub = tid & 7;
            float4 sv = *(const float4*)&sm.S[r][sub*4];
            float mold = sm.mrow[r];
            float mx = fmaxf(fmaxf(sv.x, sv.y), fmaxf(sv.z, sv.w));
            mx = fmaxf(mx, mold);
            #pragma unroll
            for (int o = 1; o < 8; o <<= 1)
                mx = fmaxf(mx, __shfl_xor_sync(0xffffffffu, mx, o));
            float e0 = __expf(sv.x - mx), e1 = __expf(sv.y - mx);
            float e2 = __expf(sv.z - mx), e3 = __expf(sv.w - mx);
            float sum = (e0+e1) + (e2+e3);
            #pragma unroll
            for (int o = 1; o < 8; o <<= 1)
                sum += __shfl_xor_sync(0xffffffffu, sum, o);
            // store P tf32-rounded (A operand of PV mma)
            float4 pv = make_float4(cvt1_tf32(e0), cvt1_tf32(e1),
                                    cvt1_tf32(e2), cvt1_tf32(e3));
            *(float4*)&sm.S[r][sub*4] = pv;
            if (sub == 0) {
                float corr = __expf(mold - mx);
                sm.crow[r] = corr;
                sm.mrow[r] = mx;
                sm.lrow[r] = sm.lrow[r]*corr + sum;
            }
        }
        __syncthreads();

        // ---- O = O*corr + P V on tensor pipe ----
        {
            const int r0 = wm*16 + g;
            const float cf0 = sm.crow[r0];
            const float cf1 = sm.crow[r0 + 8];
            #pragma unroll
            for (int nf = 0; nf < 4; nf++) {
                O[nf][0] *= cf0; O[nf][1] *= cf0;
                O[nf][2] *= cf1; O[nf][3] *= cf1;
            }
            #pragma unroll
            for (int ks = 0; ks < 4; ks++) {
                const int kk = ks*8;
                unsigned a[4];
                a[0] = __float_as_uint(sm.S[r0  ][kk+tg]);
                a[1] = __float_as_uint(sm.S[r0+8][kk+tg]);
                a[2] = __float_as_uint(sm.S[r0  ][kk+tg+4]);
                a[3] = __float_as_uint(sm.S[r0+8][kk+tg+4]);
                #pragma unroll
                for (int nf = 0; nf < 4; nf++) {
                    const int n = wn*32 + nf*8 + g;
                    unsigned bb[2];
                    bb[0] = __float_as_uint(sm.V[kk+tg  ][n]);
                    bb[1] = __float_as_uint(sm.V[kk+tg+4][n]);
                    mma_tf32(O[nf], a, bb);
                }
            }
        }
    }

    // ---- final normalize + store ----
    {
        const int r0 = wm*16 + g;
        const float inv0 = 1.0f / sm.lrow[r0];
        const float inv1 = 1.0f / sm.lrow[r0 + 8];
        const size_t ro0 = (size_t)(b*T_ + q0 + r0)*HD_;
        const size_t ro1 = ro0 + (size_t)8*HD_;
        #pragma unroll
        for (int nf = 0; nf < 4; nf++) {
            const int col = wn*32 + nf*8 + 2*tg;
            *(float2*)&out[ro0 + col] = make_float2(O[nf][0]*inv0, O[nf][1]*inv0);
            *(float2*)&out[ro1 + col] = make_float2(O[nf][2]*inv1, O[nf][3]*inv1);
        }
    }
}

// ---------------------------------------------------------------------------
extern "C" void kernel_launch(void* const* d_in, const int* in_sizes, int n_in,
                              void* d_out, int out_size)
{
    const float* x  = (const float*)d_in[0];
    const float* Wq = (const float*)d_in[1];
    const float* Wk = (const float*)d_in[2];
    const float* Wv = (const float*)d_in[3];
    const float* rc = (const float*)d_in[4];
    const float* rs = (const float*)d_in[5];
    // d_in[6] (mask) is exactly the causal -1e9 mask; computed analytically.
    float* out = (float*)d_out;

    cudaFuncSetAttribute(qkv_kernel,
                         cudaFuncAttributeMaxDynamicSharedMemorySize,
                         (int)sizeof(QkvSmem));
    cudaFuncSetAttribute(attn_kernel,
                         cudaFuncAttributeMaxDynamicSharedMemorySize,
                         (int)sizeof(AttnSmem));

    dim3 g1(MTOT/QBM, 3);
    qkv_kernel<<<g1, 256, sizeof(QkvSmem)>>>(x, Wq, Wk, Wv, rc, rs);

    attn_kernel<<<256, 256, sizeof(AttnSmem)>>>(out);
}